// round 3
// baseline (speedup 1.0000x reference)
#include <cuda_runtime.h>
#include <cuda_bf16.h>

// roi_feature: dual bilinear grid_sample with a shared 16x16 grid per batch.
// inputs: [0] original_features f32 (32,256,64,64)
//         [1] lab f32 (32,1,5)
//         [2] attack_features f32 (32,256,64,64)
// output: concat(out1, out2), each (32,256,16,16) f32.
//
// R3 strategy: dense SMEM staging. The sampled footprint is dense at sector
// granularity (bin step <= 4px < 8px sector), so coalesced row-segment loads
// have the SAME DRAM traffic as the gather but issue it as sequential float4
// loads (1 wavefront per line). 32 row slots per plane (yc0/yc1 per bin),
// x restricted to the exact sector span. Bilinear sampling then runs on SMEM.

#define B_    32
#define C_    256
#define H_    64
#define W_    64
#define BIN_  16
#define CH_PER_BLK 2
#define NPLANES (CH_PER_BLK * 2)   // 4: orig ch0, orig ch1, att ch0, att ch1
#define PITCH 68                   // 64 floats max span + pad (mult of 4 for float4)

// pixel coordinate from bin index (identical expression everywhere so float
// results match exactly between loader slot rows and sampler threads)
__device__ __forceinline__ float bin_to_pix(int idx, float scale, float center)
{
    const float g = 2.0f * (float)(idx - BIN_ / 2) * scale / (float)BIN_
                    + (center * 2.0f - 1.0f);
    return ((g + 1.0f) * 64.0f - 1.0f) * 0.5f;   // H_ == W_ == 64
}

__global__ __launch_bounds__(256)
void roi_feature_kernel(const float* __restrict__ orig,
                        const float* __restrict__ lab,
                        const float* __restrict__ att,
                        float* __restrict__ out)
{
    __shared__ float sm[NPLANES][32 * PITCH];
    __shared__ int   rows_sh[32];

    const int b      = blockIdx.x;           // 0..31
    const int cchunk = blockIdx.y;           // 0..127, 2 channels each
    const int t      = threadIdx.x;          // 0..255
    const int i      = t >> 4;               // bin row  (drives y)
    const int j      = t & 15;               // bin col  (drives x)

    const float* L = lab + b * 5;
    const float l1 = __ldg(L + 1);
    const float l2 = __ldg(L + 2);
    const float l3 = __ldg(L + 3);
    const float l4 = __ldg(L + 4);

    // ---- uniform x sector range for this batch ----
    const float xa = bin_to_pix(0,  l3, l1);
    const float xb = bin_to_pix(15, l3, l1);
    const float xlo = fminf(xa, xb);
    const float xhi = fmaxf(xa, xb);
    const int xcmin = min(max((int)floorf(xlo), 0), W_ - 1);
    const int xcmax = min(max((int)floorf(xhi) + 1, 0), W_ - 1);
    const int s_lo  = xcmin >> 3;                 // 32B sector = 8 floats
    const int s_hi  = xcmax >> 3;
    const int w4    = (s_hi - s_lo + 1) * 2;      // float4 count per row (<=16)
    const int base_px = s_lo * 8;

    // ---- slot rows (threads 0..31) ----
    if (t < 32) {
        const int bi = t >> 1;
        const float yy = bin_to_pix(bi, l4, l2);
        const int y0 = (int)floorf(yy);
        const int yc0 = min(max(y0, 0), H_ - 1);
        const int yc1 = min(max(y0 + 1, 0), H_ - 1);
        rows_sh[t] = (t & 1) ? yc1 : yc0;
    }
    __syncthreads();

    // ---- load phase: coalesced float4 row segments into SMEM ----
    {
        const size_t plane = (size_t)H_ * W_;     // 4096
        const size_t base  = ((size_t)b * C_ + (size_t)cchunk * CH_PER_BLK) * plane;
        const float* pl[NPLANES] = {
            orig + base, orig + base + plane,
            att  + base, att  + base + plane
        };
        const int r = t >> 4;                     // slot pair base (0..15)
        const int l = t & 15;                     // float4 lane within row
        if (l < w4) {
            const int slotA = r;
            const int slotB = r + 16;
            const int rowA = rows_sh[slotA];
            const int rowB = rows_sh[slotB];
            const int offA = rowA * W_ + base_px + 4 * l;
            const int offB = rowB * W_ + base_px + 4 * l;
            #pragma unroll
            for (int p = 0; p < NPLANES; ++p) {
                const float4 vA = *(const float4*)(pl[p] + offA);
                const float4 vB = *(const float4*)(pl[p] + offB);
                *(float4*)(&sm[p][slotA * PITCH + 4 * l]) = vA;
                *(float4*)(&sm[p][slotB * PITCH + 4 * l]) = vB;
            }
        }
    }

    // ---- per-thread bilinear setup ----
    const float x = bin_to_pix(j, l3, l1);
    const float y = bin_to_pix(i, l4, l2);

    const float x0f = floorf(x);
    const float y0f = floorf(y);
    const int x0 = (int)x0f;
    const int y0 = (int)y0f;
    const int x1 = x0 + 1;
    const int y1 = y0 + 1;

    const float wx1 = x - x0f, wx0 = 1.0f - wx1;
    const float wy1 = y - y0f, wy0 = 1.0f - wy1;

    const float vx0 = (x0 >= 0 && x0 < W_) ? 1.0f : 0.0f;
    const float vx1 = (x1 >= 0 && x1 < W_) ? 1.0f : 0.0f;
    const float vy0 = (y0 >= 0 && y0 < H_) ? 1.0f : 0.0f;
    const float vy1 = (y1 >= 0 && y1 < H_) ? 1.0f : 0.0f;

    const float w00 = wx0 * wy0 * vx0 * vy0;
    const float w01 = wx1 * wy0 * vx1 * vy0;
    const float w10 = wx0 * wy1 * vx0 * vy1;
    const float w11 = wx1 * wy1 * vx1 * vy1;

    const int dx0 = min(max(x0, 0), W_ - 1) - base_px;
    const int dx1 = min(max(x1, 0), W_ - 1) - base_px;
    const int s0  = (2 * i) * PITCH;       // slot for yc0(i)
    const int s1  = (2 * i + 1) * PITCH;   // slot for yc1(i)

    __syncthreads();

    // ---- sample phase: bilinear from SMEM, write both outputs ----
    const size_t outbase = ((size_t)b * C_ + (size_t)cchunk * CH_PER_BLK) * (BIN_ * BIN_) + t;
    const size_t out2off = (size_t)B_ * C_ * BIN_ * BIN_;   // 2,097,152

    #pragma unroll
    for (int cc = 0; cc < CH_PER_BLK; ++cc) {
        const float* P = sm[cc];              // orig plane cc
        const float* Q = sm[CH_PER_BLK + cc]; // att  plane cc
        const float r1 = P[s0 + dx0] * w00 + P[s0 + dx1] * w01
                       + P[s1 + dx0] * w10 + P[s1 + dx1] * w11;
        const float r2 = Q[s0 + dx0] * w00 + Q[s0 + dx1] * w01
                       + Q[s1 + dx0] * w10 + Q[s1 + dx1] * w11;
        out[outbase + (size_t)cc * (BIN_ * BIN_)]           = r1;
        out[out2off + outbase + (size_t)cc * (BIN_ * BIN_)] = r2;
    }
}

extern "C" void kernel_launch(void* const* d_in, const int* in_sizes, int n_in,
                              void* d_out, int out_size)
{
    const float* orig = (const float*)d_in[0];
    const float* lab  = (const float*)d_in[1];
    const float* att  = (const float*)d_in[2];
    float* out        = (float*)d_out;

    dim3 grid(B_, C_ / CH_PER_BLK);   // (32, 128)
    roi_feature_kernel<<<grid, 256>>>(orig, lab, att, out);
}

// round 4
// speedup vs baseline: 1.6275x; 1.6275x over previous
#include <cuda_runtime.h>
#include <cuda_bf16.h>

// roi_feature: dual bilinear grid_sample with a shared 16x16 grid per batch.
// inputs: [0] original_features f32 (32,256,64,64)
//         [1] lab f32 (32,1,5)
//         [2] attack_features f32 (32,256,64,64)
// output: concat(out1, out2), each (32,256,16,16) f32.
//
// R4 strategy: R2 kernel (front-batched 32-load gather, CH_PER_BLK=4) with
// the grid order swapped: channel-chunk is now blockIdx.x (fast-varying), so
// concurrently-resident blocks read adjacent 16KB channel planes instead of
// striping across the full 256MB — clustered DRAM sector streams for better
// row-buffer behavior.

#define B_   32
#define C_   256
#define H_   64
#define W_   64
#define BIN_ 16
#define CH_PER_BLK 4

__global__ __launch_bounds__(256, 4)
void roi_feature_kernel(const float* __restrict__ orig,
                        const float* __restrict__ lab,
                        const float* __restrict__ att,
                        float* __restrict__ out)
{
    const int cchunk = blockIdx.x;           // 0..63, 4 channels each (fast)
    const int b      = blockIdx.y;           // 0..31
    const int t      = threadIdx.x;          // 0..255
    const int i      = t >> 4;               // bin row  (drives y)
    const int j      = t & 15;               // bin col  (drives x)

    const float* L = lab + b * 5;
    const float l1 = __ldg(L + 1);
    const float l2 = __ldg(L + 2);
    const float l3 = __ldg(L + 3);
    const float l4 = __ldg(L + 4);

    // grid[...,0] = mesh_y[b, j] -> x pixel; grid[...,1] = mesh_x[b, i] -> y pixel
    const float gx = 2.0f * (float)(j - BIN_ / 2) * l3 / (float)BIN_ + (l1 * 2.0f - 1.0f);
    const float gy = 2.0f * (float)(i - BIN_ / 2) * l4 / (float)BIN_ + (l2 * 2.0f - 1.0f);

    const float x = ((gx + 1.0f) * (float)W_ - 1.0f) * 0.5f;
    const float y = ((gy + 1.0f) * (float)H_ - 1.0f) * 0.5f;

    const float x0f = floorf(x);
    const float y0f = floorf(y);
    const int x0 = (int)x0f;
    const int y0 = (int)y0f;
    const int x1 = x0 + 1;
    const int y1 = y0 + 1;

    const float wx1 = x - x0f, wx0 = 1.0f - wx1;
    const float wy1 = y - y0f, wy0 = 1.0f - wy1;

    const float vx0 = (x0 >= 0 && x0 < W_) ? 1.0f : 0.0f;
    const float vx1 = (x1 >= 0 && x1 < W_) ? 1.0f : 0.0f;
    const float vy0 = (y0 >= 0 && y0 < H_) ? 1.0f : 0.0f;
    const float vy1 = (y1 >= 0 && y1 < H_) ? 1.0f : 0.0f;

    const float w00 = wx0 * wy0 * vx0 * vy0;
    const float w01 = wx1 * wy0 * vx1 * vy0;
    const float w10 = wx0 * wy1 * vx0 * vy1;
    const float w11 = wx1 * wy1 * vx1 * vy1;

    const int xc0 = min(max(x0, 0), W_ - 1);
    const int xc1 = min(max(x1, 0), W_ - 1);
    const int yc0 = min(max(y0, 0), H_ - 1);
    const int yc1 = min(max(y1, 0), H_ - 1);

    const int o00 = yc0 * W_ + xc0;
    const int o01 = yc0 * W_ + xc1;
    const int o10 = yc1 * W_ + xc0;
    const int o11 = yc1 * W_ + xc1;

    const size_t plane   = (size_t)H_ * W_;                     // 4096
    const size_t base    = ((size_t)b * C_ + (size_t)cchunk * CH_PER_BLK) * plane;
    const size_t outbase = ((size_t)b * C_ + (size_t)cchunk * CH_PER_BLK) * (BIN_ * BIN_) + t;
    const size_t out2off = (size_t)B_ * C_ * BIN_ * BIN_;       // 2,097,152

    // ---- Phase 1: issue ALL gather loads (32 in flight per thread) ----
    float p[CH_PER_BLK][4];
    float q[CH_PER_BLK][4];

    #pragma unroll
    for (int cc = 0; cc < CH_PER_BLK; ++cc) {
        const float* pp = orig + base + (size_t)cc * plane;
        p[cc][0] = __ldg(pp + o00);
        p[cc][1] = __ldg(pp + o01);
        p[cc][2] = __ldg(pp + o10);
        p[cc][3] = __ldg(pp + o11);
    }
    #pragma unroll
    for (int cc = 0; cc < CH_PER_BLK; ++cc) {
        const float* qq = att + base + (size_t)cc * plane;
        q[cc][0] = __ldg(qq + o00);
        q[cc][1] = __ldg(qq + o01);
        q[cc][2] = __ldg(qq + o10);
        q[cc][3] = __ldg(qq + o11);
    }

    // ---- Phase 2: compute + store ----
    #pragma unroll
    for (int cc = 0; cc < CH_PER_BLK; ++cc) {
        const float r1 = p[cc][0] * w00 + p[cc][1] * w01 + p[cc][2] * w10 + p[cc][3] * w11;
        const float r2 = q[cc][0] * w00 + q[cc][1] * w01 + q[cc][2] * w10 + q[cc][3] * w11;
        out[outbase + (size_t)cc * (BIN_ * BIN_)]           = r1;
        out[out2off + outbase + (size_t)cc * (BIN_ * BIN_)] = r2;
    }
}

extern "C" void kernel_launch(void* const* d_in, const int* in_sizes, int n_in,
                              void* d_out, int out_size)
{
    const float* orig = (const float*)d_in[0];
    const float* lab  = (const float*)d_in[1];
    const float* att  = (const float*)d_in[2];
    float* out        = (float*)d_out;

    dim3 grid(C_ / CH_PER_BLK, B_);   // (64, 32): channel-chunk fast-varying
    roi_feature_kernel<<<grid, 256>>>(orig, lab, att, out);
}

// round 5
// speedup vs baseline: 1.6355x; 1.0049x over previous
#include <cuda_runtime.h>
#include <cuda_bf16.h>

// roi_feature: dual bilinear grid_sample with a shared 16x16 grid per batch.
// inputs: [0] original_features f32 (32,256,64,64)
//         [1] lab f32 (32,1,5)
//         [2] attack_features f32 (32,256,64,64)
// output: concat(out1, out2), each (32,256,16,16) f32.
//
// R5 strategy: single-wave persistent loop. 592 blocks (148 SMs x 4 resident)
// grid-stride over 2048 (b, cchunk) tasks. Eliminates wave-transition gaps and
// the front-batched-MLP cross-CTA spread penalty (B300 spr_max ~2x at
// MLP_p1=32), while the loop overlaps each iteration's FMAs/stores with the
// next iteration's 32 front-batched gather loads.

#define B_   32
#define C_   256
#define H_   64
#define W_   64
#define BIN_ 16
#define CH_PER_BLK 4
#define NTASKS (B_ * (C_ / CH_PER_BLK))   // 2048
#define NBLOCKS 592

__global__ __launch_bounds__(256, 4)
void roi_feature_kernel(const float* __restrict__ orig,
                        const float* __restrict__ lab,
                        const float* __restrict__ att,
                        float* __restrict__ out)
{
    const int t = threadIdx.x;          // 0..255
    const int i = t >> 4;               // bin row  (drives y)
    const int j = t & 15;               // bin col  (drives x)

    const size_t plane   = (size_t)H_ * W_;                 // 4096
    const size_t out2off = (size_t)B_ * C_ * BIN_ * BIN_;   // 2,097,152

    for (int task = blockIdx.x; task < NTASKS; task += NBLOCKS) {
        const int b      = task >> 6;        // 0..31
        const int cchunk = task & 63;        // 0..63

        const float* L = lab + b * 5;
        const float l1 = __ldg(L + 1);
        const float l2 = __ldg(L + 2);
        const float l3 = __ldg(L + 3);
        const float l4 = __ldg(L + 4);

        // grid[...,0] -> x pixel (from j); grid[...,1] -> y pixel (from i)
        const float gx = 2.0f * (float)(j - BIN_ / 2) * l3 / (float)BIN_ + (l1 * 2.0f - 1.0f);
        const float gy = 2.0f * (float)(i - BIN_ / 2) * l4 / (float)BIN_ + (l2 * 2.0f - 1.0f);

        const float x = ((gx + 1.0f) * (float)W_ - 1.0f) * 0.5f;
        const float y = ((gy + 1.0f) * (float)H_ - 1.0f) * 0.5f;

        const float x0f = floorf(x);
        const float y0f = floorf(y);
        const int x0 = (int)x0f;
        const int y0 = (int)y0f;
        const int x1 = x0 + 1;
        const int y1 = y0 + 1;

        const float wx1 = x - x0f, wx0 = 1.0f - wx1;
        const float wy1 = y - y0f, wy0 = 1.0f - wy1;

        const float vx0 = (x0 >= 0 && x0 < W_) ? 1.0f : 0.0f;
        const float vx1 = (x1 >= 0 && x1 < W_) ? 1.0f : 0.0f;
        const float vy0 = (y0 >= 0 && y0 < H_) ? 1.0f : 0.0f;
        const float vy1 = (y1 >= 0 && y1 < H_) ? 1.0f : 0.0f;

        const float w00 = wx0 * wy0 * vx0 * vy0;
        const float w01 = wx1 * wy0 * vx1 * vy0;
        const float w10 = wx0 * wy1 * vx0 * vy1;
        const float w11 = wx1 * wy1 * vx1 * vy1;

        const int xc0 = min(max(x0, 0), W_ - 1);
        const int xc1 = min(max(x1, 0), W_ - 1);
        const int yc0 = min(max(y0, 0), H_ - 1);
        const int yc1 = min(max(y1, 0), H_ - 1);

        const int o00 = yc0 * W_ + xc0;
        const int o01 = yc0 * W_ + xc1;
        const int o10 = yc1 * W_ + xc0;
        const int o11 = yc1 * W_ + xc1;

        const size_t base    = ((size_t)b * C_ + (size_t)cchunk * CH_PER_BLK) * plane;
        const size_t outbase = ((size_t)b * C_ + (size_t)cchunk * CH_PER_BLK) * (BIN_ * BIN_) + t;

        // ---- Phase 1: issue ALL gather loads (32 in flight per thread) ----
        float p[CH_PER_BLK][4];
        float q[CH_PER_BLK][4];

        #pragma unroll
        for (int cc = 0; cc < CH_PER_BLK; ++cc) {
            const float* pp = orig + base + (size_t)cc * plane;
            p[cc][0] = __ldg(pp + o00);
            p[cc][1] = __ldg(pp + o01);
            p[cc][2] = __ldg(pp + o10);
            p[cc][3] = __ldg(pp + o11);
        }
        #pragma unroll
        for (int cc = 0; cc < CH_PER_BLK; ++cc) {
            const float* qq = att + base + (size_t)cc * plane;
            q[cc][0] = __ldg(qq + o00);
            q[cc][1] = __ldg(qq + o01);
            q[cc][2] = __ldg(qq + o10);
            q[cc][3] = __ldg(qq + o11);
        }

        // ---- Phase 2: compute + store ----
        #pragma unroll
        for (int cc = 0; cc < CH_PER_BLK; ++cc) {
            const float r1 = p[cc][0] * w00 + p[cc][1] * w01 + p[cc][2] * w10 + p[cc][3] * w11;
            const float r2 = q[cc][0] * w00 + q[cc][1] * w01 + q[cc][2] * w10 + q[cc][3] * w11;
            out[outbase + (size_t)cc * (BIN_ * BIN_)]           = r1;
            out[out2off + outbase + (size_t)cc * (BIN_ * BIN_)] = r2;
        }
    }
}

extern "C" void kernel_launch(void* const* d_in, const int* in_sizes, int n_in,
                              void* d_out, int out_size)
{
    const float* orig = (const float*)d_in[0];
    const float* lab  = (const float*)d_in[1];
    const float* att  = (const float*)d_in[2];
    float* out        = (float*)d_out;

    roi_feature_kernel<<<NBLOCKS, 256>>>(orig, lab, att, out);
}

// round 6
// speedup vs baseline: 1.6642x; 1.0175x over previous
#include <cuda_runtime.h>
#include <cuda_bf16.h>

// roi_feature: dual bilinear grid_sample with a shared 16x16 grid per batch.
// inputs: [0] original_features f32 (32,256,64,64)
//         [1] lab f32 (32,1,5)
//         [2] attack_features f32 (32,256,64,64)
// output: concat(out1, out2), each (32,256,16,16) f32.
//
// R6 strategy: make the load front-batch REAL. R2's launch_bounds(256,4)
// capped regs at 48, so ptxas could only keep ~12 loads in flight. Now
// launch_bounds(256,2) (<=128 regs) + CH_PER_BLK=8: 64 gather loads per
// thread genuinely batched before any consume -> MLP high enough to keep
// DRAM saturated through its 577-cyc latency.

#define B_   32
#define C_   256
#define H_   64
#define W_   64
#define BIN_ 16
#define CH_PER_BLK 8

__global__ __launch_bounds__(256, 2)
void roi_feature_kernel(const float* __restrict__ orig,
                        const float* __restrict__ lab,
                        const float* __restrict__ att,
                        float* __restrict__ out)
{
    const int b      = blockIdx.x;           // 0..31
    const int cchunk = blockIdx.y;           // 0..31, 8 channels each
    const int t      = threadIdx.x;          // 0..255
    const int i      = t >> 4;               // bin row  (drives y)
    const int j      = t & 15;               // bin col  (drives x)

    const float* L = lab + b * 5;
    const float l1 = __ldg(L + 1);
    const float l2 = __ldg(L + 2);
    const float l3 = __ldg(L + 3);
    const float l4 = __ldg(L + 4);

    // grid[...,0] -> x pixel (from j); grid[...,1] -> y pixel (from i)
    const float gx = 2.0f * (float)(j - BIN_ / 2) * l3 / (float)BIN_ + (l1 * 2.0f - 1.0f);
    const float gy = 2.0f * (float)(i - BIN_ / 2) * l4 / (float)BIN_ + (l2 * 2.0f - 1.0f);

    const float x = ((gx + 1.0f) * (float)W_ - 1.0f) * 0.5f;
    const float y = ((gy + 1.0f) * (float)H_ - 1.0f) * 0.5f;

    const float x0f = floorf(x);
    const float y0f = floorf(y);
    const int x0 = (int)x0f;
    const int y0 = (int)y0f;
    const int x1 = x0 + 1;
    const int y1 = y0 + 1;

    const float wx1 = x - x0f, wx0 = 1.0f - wx1;
    const float wy1 = y - y0f, wy0 = 1.0f - wy1;

    const float vx0 = (x0 >= 0 && x0 < W_) ? 1.0f : 0.0f;
    const float vx1 = (x1 >= 0 && x1 < W_) ? 1.0f : 0.0f;
    const float vy0 = (y0 >= 0 && y0 < H_) ? 1.0f : 0.0f;
    const float vy1 = (y1 >= 0 && y1 < H_) ? 1.0f : 0.0f;

    const float w00 = wx0 * wy0 * vx0 * vy0;
    const float w01 = wx1 * wy0 * vx1 * vy0;
    const float w10 = wx0 * wy1 * vx0 * vy1;
    const float w11 = wx1 * wy1 * vx1 * vy1;

    const int xc0 = min(max(x0, 0), W_ - 1);
    const int xc1 = min(max(x1, 0), W_ - 1);
    const int yc0 = min(max(y0, 0), H_ - 1);
    const int yc1 = min(max(y1, 0), H_ - 1);

    const int o00 = yc0 * W_ + xc0;
    const int o01 = yc0 * W_ + xc1;
    const int o10 = yc1 * W_ + xc0;
    const int o11 = yc1 * W_ + xc1;

    const size_t plane   = (size_t)H_ * W_;                     // 4096
    const size_t base    = ((size_t)b * C_ + (size_t)cchunk * CH_PER_BLK) * plane;
    const size_t outbase = ((size_t)b * C_ + (size_t)cchunk * CH_PER_BLK) * (BIN_ * BIN_) + t;
    const size_t out2off = (size_t)B_ * C_ * BIN_ * BIN_;       // 2,097,152

    // ---- Phase 1: issue ALL 64 gather loads before any consume ----
    float p[CH_PER_BLK][4];
    float q[CH_PER_BLK][4];

    #pragma unroll
    for (int cc = 0; cc < CH_PER_BLK; ++cc) {
        const float* pp = orig + base + (size_t)cc * plane;
        p[cc][0] = __ldg(pp + o00);
        p[cc][1] = __ldg(pp + o01);
        p[cc][2] = __ldg(pp + o10);
        p[cc][3] = __ldg(pp + o11);
    }
    #pragma unroll
    for (int cc = 0; cc < CH_PER_BLK; ++cc) {
        const float* qq = att + base + (size_t)cc * plane;
        q[cc][0] = __ldg(qq + o00);
        q[cc][1] = __ldg(qq + o01);
        q[cc][2] = __ldg(qq + o10);
        q[cc][3] = __ldg(qq + o11);
    }

    // ---- Phase 2: compute + store ----
    #pragma unroll
    for (int cc = 0; cc < CH_PER_BLK; ++cc) {
        const float r1 = p[cc][0] * w00 + p[cc][1] * w01 + p[cc][2] * w10 + p[cc][3] * w11;
        const float r2 = q[cc][0] * w00 + q[cc][1] * w01 + q[cc][2] * w10 + q[cc][3] * w11;
        out[outbase + (size_t)cc * (BIN_ * BIN_)]           = r1;
        out[out2off + outbase + (size_t)cc * (BIN_ * BIN_)] = r2;
    }
}

extern "C" void kernel_launch(void* const* d_in, const int* in_sizes, int n_in,
                              void* d_out, int out_size)
{
    const float* orig = (const float*)d_in[0];
    const float* lab  = (const float*)d_in[1];
    const float* att  = (const float*)d_in[2];
    float* out        = (float*)d_out;

    dim3 grid(B_, C_ / CH_PER_BLK);   // (32, 32)
    roi_feature_kernel<<<grid, 256>>>(orig, lab, att, out);
}